// round 10
// baseline (speedup 1.0000x reference)
#include <cuda_runtime.h>
#include <cuda_fp16.h>
#include <cstdint>

#define BATCH   8
#define SEQ     512
#define DIM     1024
#define HEADS   16
#define HD      64
#define NPATCH  196
#define MROWS   (BATCH*SEQ)     /* 4096 */
#define BH      (BATCH*HEADS)   /* 128  */

// ---------------- scratch (device globals: allocation-free) ----------------
__device__ __half g_xh [(size_t)MROWS*DIM];          // x hi
__device__ __half g_wh [(size_t)3*DIM*DIM];          // wq,wk,wv hi
__device__ __half g_woh[(size_t)DIM*DIM];            // wo hi
__device__ __half g_qh [(size_t)BH*SEQ*HD];          // Q hi (pre-scaled by 1/8)
__device__ __half g_kh [(size_t)BH*SEQ*HD];          // K hi
__device__ __half g_vh [(size_t)BH*HD*SEQ];          // V hi, [B,H,hd,S]
__device__ __half g_ch [(size_t)MROWS*DIM];          // ctx hi [B,S,D]

__device__ __forceinline__ float neg_inf() { return __int_as_float(0xff800000); }
__device__ __forceinline__ bool okqk(int q, int k)
{ return (q < NPATCH) ? (k < NPATCH) : (k <= q); }

// ===========================================================================
//  fused split kernel: x (4096 blocks) + 4 weights (1024 blocks each)
// ===========================================================================
__global__ __launch_bounds__(256) void split_all(const float* __restrict__ x,
                                                 const float* __restrict__ wq,
                                                 const float* __restrict__ wk,
                                                 const float* __restrict__ wv,
                                                 const float* __restrict__ wo)
{
    const float* src;
    __half* dst;
    size_t i;
    if (blockIdx.x < 4096) {
        src = x; dst = g_xh;
        i = (size_t)blockIdx.x * 256 + threadIdx.x;
    } else {
        int w = blockIdx.x - 4096;
        int seg = w >> 10;
        src = (seg == 0) ? wq : (seg == 1) ? wk : (seg == 2) ? wv : wo;
        dst = (seg < 3) ? g_wh + (size_t)seg * DIM * DIM : g_woh;
        i = (size_t)(w & 1023) * 256 + threadIdx.x;
    }
    float4 v = ((const float4*)src)[i];
    ((__half2*)dst)[i*2+0] = __halves2half2(__float2half(v.x), __float2half(v.y));
    ((__half2*)dst)[i*2+1] = __halves2half2(__float2half(v.z), __float2half(v.w));
}

// ===========================================================================
//  common utils
// ===========================================================================
__device__ __forceinline__ uint32_t smem_u32(const void* p)
{ return (uint32_t)__cvta_generic_to_shared(p); }

__device__ __forceinline__ void cp_async16(uint32_t s, const void* g)
{ asm volatile("cp.async.cg.shared.global [%0], [%1], 16;\n" :: "r"(s), "l"(g)); }

__device__ __forceinline__ void ldsm4(uint32_t addr, uint32_t* r)
{
    asm volatile("ldmatrix.sync.aligned.m8n8.x4.shared.b16 {%0,%1,%2,%3}, [%4];"
                 : "=r"(r[0]), "=r"(r[1]), "=r"(r[2]), "=r"(r[3]) : "r"(addr));
}

__device__ __forceinline__ void mma16(float* c, const uint32_t* a, const uint32_t* b)
{
    asm volatile(
        "mma.sync.aligned.m16n8k16.row.col.f32.f16.f16.f32 "
        "{%0,%1,%2,%3},{%4,%5,%6,%7},{%8,%9},{%0,%1,%2,%3};"
        : "+f"(c[0]), "+f"(c[1]), "+f"(c[2]), "+f"(c[3])
        : "r"(a[0]), "r"(a[1]), "r"(a[2]), "r"(a[3]), "r"(b[0]), "r"(b[1]));
}

// ===========================================================================
//  1-term fp16 128x128xK GEMM (projections). 3-stage cp.async pipeline.
//  8 warps 2(M)x4(N), warp tile 64x32. 2 CTAs/SM.
// ===========================================================================
#define BK       32
#define PAD      40
#define A_TEH    (128*PAD)          /* halves per tile (A or B) */
#define STAGE_H  (2*A_TEH)          /* 10240 halves             */
#define PRJ_SMEM (3*STAGE_H*2)      /* 61440 bytes              */
#define PRJ_NKT  (DIM/BK)           /* 32                       */

__device__ __forceinline__ void gemm1(
    const __half* __restrict__ Ah, const __half* __restrict__ Bh,
    __half* sm, float (&acc)[4][4][4])
{
    const int tid  = threadIdx.x;
    const int warp = tid >> 5, lane = tid & 31;
    const int wm0  = (warp & 1) << 6;       // 0/64
    const int wn0  = (warp >> 1) << 5;      // 0,32,64,96
    const int a_row = (lane & 7) + ((lane >> 3) & 1) * 8;
    const int a_k   = ((lane >> 4) & 1) * 8;
    const int b_row = (lane & 7) + ((lane >> 4) & 1) * 8;
    const int b_k   = ((lane >> 3) & 1) * 8;
    const uint32_t sb = smem_u32(sm);

    auto load_stage = [&](int kt, int s) {
        uint32_t st = sb + (uint32_t)s * STAGE_H * 2;
        #pragma unroll
        for (int c = 0; c < 2; ++c) {
            int idx = tid + c * 256;
            int row = idx >> 2, ch = idx & 3;
            cp_async16(st + (uint32_t)(row * PAD + ch * 8) * 2,
                       Ah + (size_t)row * DIM + kt * BK + ch * 8);
            cp_async16(st + (uint32_t)(A_TEH + row * PAD + ch * 8) * 2,
                       Bh + (size_t)row * DIM + kt * BK + ch * 8);
        }
    };

    load_stage(0, 0);
    asm volatile("cp.async.commit_group;\n" ::: "memory");
    load_stage(1, 1);
    asm volatile("cp.async.commit_group;\n" ::: "memory");

    for (int kt = 0; kt < PRJ_NKT; ++kt) {
        const int cur = kt % 3;
        if (kt + 2 < PRJ_NKT) {
            load_stage(kt + 2, (kt + 2) % 3);
            asm volatile("cp.async.commit_group;\n" ::: "memory");
            asm volatile("cp.async.wait_group 2;\n" ::: "memory");
        } else if (kt + 1 < PRJ_NKT) {
            asm volatile("cp.async.wait_group 1;\n" ::: "memory");
        } else {
            asm volatile("cp.async.wait_group 0;\n" ::: "memory");
        }
        __syncthreads();

        const uint32_t st  = sb + (uint32_t)cur * STAGE_H * 2;
        const uint32_t sAh = st;
        const uint32_t sBh = st + A_TEH * 2;

        #pragma unroll
        for (int ks = 0; ks < BK; ks += 16) {
            uint32_t b[4][2];
            #pragma unroll
            for (int jj = 0; jj < 2; ++jj) {
                uint32_t r[4];
                ldsm4(sBh + (uint32_t)((wn0 + jj*16 + b_row) * PAD + ks + b_k) * 2, r);
                b[jj*2+0][0] = r[0]; b[jj*2+0][1] = r[1];
                b[jj*2+1][0] = r[2]; b[jj*2+1][1] = r[3];
            }
            uint32_t af[4][4];
            #pragma unroll
            for (int i = 0; i < 4; ++i)
                ldsm4(sAh + (uint32_t)((wm0 + i*16 + a_row) * PAD + ks + a_k) * 2, af[i]);
            #pragma unroll
            for (int i = 0; i < 4; ++i)
                #pragma unroll
                for (int j = 0; j < 4; ++j) mma16(acc[i][j], af[i], b[j]);
        }
        __syncthreads();
    }
}

// ---- 1) QKV projection: Q hi (scaled by 1/8), K hi, V hi transposed --------
__global__ __launch_bounds__(256, 2) void qkv_mma()
{
    extern __shared__ __half sm[];
    const int z = blockIdx.z;
    const __half* Ah = g_xh + (size_t)blockIdx.y * 128 * DIM;
    const __half* Bh = g_wh + (size_t)z * DIM * DIM + (size_t)blockIdx.x * 128 * DIM;

    float acc[4][4][4] = {};
    gemm1(Ah, Bh, sm, acc);

    const int warp = threadIdx.x >> 5, lane = threadIdx.x & 31;
    const int g = lane >> 2, t2 = (lane & 3) << 1;
    const int wm0 = (warp & 1) << 6, wn0 = (warp >> 1) << 5;
    #pragma unroll
    for (int i = 0; i < 4; ++i)
        #pragma unroll
        for (int j = 0; j < 4; ++j)
            #pragma unroll
            for (int r = 0; r < 4; ++r) {
                int m = blockIdx.y * 128 + wm0 + i * 16 + g + ((r >= 2) ? 8 : 0);
                int n = blockIdx.x * 128 + wn0 + j * 8 + t2 + (r & 1);
                int b = m >> 9, s = m & 511, h = n >> 6, d = n & 63;
                float v = acc[i][j][r];
                if (z == 0) {
                    size_t idx = ((size_t)(b * HEADS + h) * SEQ + s) * HD + d;
                    g_qh[idx] = __float2half(v * 0.125f);
                } else if (z == 1) {
                    size_t idx = ((size_t)(b * HEADS + h) * SEQ + s) * HD + d;
                    g_kh[idx] = __float2half(v);
                } else {
                    size_t idx = ((size_t)(b * HEADS + h) * HD + d) * SEQ + s;
                    g_vh[idx] = __float2half(v);
                }
            }
}

// ---- 5) out projection + bias ----------------------------------------------
__global__ __launch_bounds__(256, 2) void out_mma(const float* __restrict__ bo,
                                                  float* __restrict__ out)
{
    extern __shared__ __half sm[];
    const __half* Ah = g_ch + (size_t)blockIdx.y * 128 * DIM;
    const __half* Bh = g_woh + (size_t)blockIdx.x * 128 * DIM;

    float acc[4][4][4] = {};
    gemm1(Ah, Bh, sm, acc);

    const int warp = threadIdx.x >> 5, lane = threadIdx.x & 31;
    const int g = lane >> 2, t2 = (lane & 3) << 1;
    const int wm0 = (warp & 1) << 6, wn0 = (warp >> 1) << 5;
    #pragma unroll
    for (int i = 0; i < 4; ++i)
        #pragma unroll
        for (int j = 0; j < 4; ++j)
            #pragma unroll
            for (int r = 0; r < 4; ++r) {
                int m = blockIdx.y * 128 + wm0 + i * 16 + g + ((r >= 2) ? 8 : 0);
                int n = blockIdx.x * 128 + wn0 + j * 8 + t2 + (r & 1);
                out[(size_t)m * DIM + n] = acc[i][j][r] + bo[n];
            }
}

// ===========================================================================
//  fused flash attention: 128-thread CTA, 4 warps x 16 q rows (q-tile 64).
//  grid (8 qtiles, 128 bh) -> 1024 CTAs, 2 CTAs/SM.
// ===========================================================================
#define FA_PADK 72
#define FA_PADV 136
#define FA_KH   (128*FA_PADK)            /* halves */
#define FA_VT   (64*FA_PADV)
#define FA_STAGE_H (FA_KH + FA_VT)       /* 17920 halves */
#define FA_Q_H  (64*FA_PADK)             /* 4608 halves  */
#define FA_SMEM ((FA_Q_H + 2*FA_STAGE_H)*2)   /* 80896 B */

__global__ __launch_bounds__(128) void flash_attn()
{
    extern __shared__ __half fsm[];
    const int qt = blockIdx.x, bh = blockIdx.y;
    const int tid = threadIdx.x, warp = tid >> 5, lane = tid & 31;
    const int g = lane >> 2, t2 = (lane & 3) << 1;
    const int a_row = (lane & 7) + ((lane >> 3) & 1) * 8;
    const int a_k   = ((lane >> 4) & 1) * 8;
    const int b_row = (lane & 7) + ((lane >> 4) & 1) * 8;
    const int b_k   = ((lane >> 3) & 1) * 8;

    const int NT8[8] = {2, 2, 2, 2, 3, 3, 4, 4};
    const int ntiles = NT8[qt];

    const __half* Qh = g_qh + ((size_t)bh * SEQ + qt * 64) * HD;
    const __half* Kh = g_kh + (size_t)bh * SEQ * HD;
    const __half* Vt = g_vh + (size_t)bh * HD * SEQ;

    const uint32_t sb  = smem_u32(fsm);
    const uint32_t sQh = sb;
    const uint32_t sStg = sb + (uint32_t)FA_Q_H * 2;

    #pragma unroll
    for (int c = 0; c < 4; ++c) {
        int idx = tid + c * 128;
        int row = idx >> 3, ch = idx & 7;
        cp_async16(sQh + (uint32_t)(row * FA_PADK + ch * 8) * 2, Qh + (size_t)row * HD + ch * 8);
    }
    asm volatile("cp.async.commit_group;\n" ::: "memory");

    auto load_kv = [&](int t, int s) {
        uint32_t st = sStg + (uint32_t)s * FA_STAGE_H * 2;
        #pragma unroll
        for (int c = 0; c < 8; ++c) {
            int idx = tid + c * 128;
            int row = idx >> 3, ch = idx & 7;
            cp_async16(st + (uint32_t)(row * FA_PADK + ch * 8) * 2,
                       Kh + (size_t)(t * 128 + row) * HD + ch * 8);
        }
        uint32_t sv = st + (uint32_t)FA_KH * 2;
        #pragma unroll
        for (int c = 0; c < 8; ++c) {
            int idx = tid + c * 128;
            int row = idx >> 4, ch = idx & 15;
            cp_async16(sv + (uint32_t)(row * FA_PADV + ch * 8) * 2,
                       Vt + (size_t)row * SEQ + t * 128 + ch * 8);
        }
    };

    load_kv(0, 0);
    asm volatile("cp.async.commit_group;\n" ::: "memory");

    asm volatile("cp.async.wait_group 1;\n" ::: "memory");
    __syncthreads();
    uint32_t qfh[4][4];
    #pragma unroll
    for (int ks = 0; ks < 4; ++ks)
        ldsm4(sQh + (uint32_t)((warp * 16 + a_row) * FA_PADK + ks * 16 + a_k) * 2, qfh[ks]);

    float acc_o[8][4] = {};
    float m0 = neg_inf(), m1 = neg_inf(), l0 = 0.f, l1 = 0.f;

    for (int t = 0; t < ntiles; ++t) {
        if (t + 1 < ntiles) {
            load_kv(t + 1, (t + 1) & 1);
            asm volatile("cp.async.commit_group;\n" ::: "memory");
            asm volatile("cp.async.wait_group 1;\n" ::: "memory");
        } else {
            asm volatile("cp.async.wait_group 0;\n" ::: "memory");
        }
        __syncthreads();

        const uint32_t st = sStg + (uint32_t)(t & 1) * FA_STAGE_H * 2;
        const uint32_t sK = st;
        const uint32_t sV = st + (uint32_t)FA_KH * 2;

        float s[16][4];
        #pragma unroll
        for (int j = 0; j < 16; ++j)
            #pragma unroll
            for (int r = 0; r < 4; ++r) s[j][r] = 0.f;

        #pragma unroll
        for (int ks = 0; ks < 4; ++ks) {
            uint32_t bfr[16][2];
            #pragma unroll
            for (int jj = 0; jj < 8; ++jj) {
                uint32_t r[4];
                ldsm4(sK + (uint32_t)((jj*16 + b_row) * FA_PADK + ks*16 + b_k) * 2, r);
                bfr[jj*2+0][0] = r[0]; bfr[jj*2+0][1] = r[1];
                bfr[jj*2+1][0] = r[2]; bfr[jj*2+1][1] = r[3];
            }
            #pragma unroll
            for (int j = 0; j < 16; ++j)
                mma16(s[j], qfh[ks], bfr[j]);
        }

        if (t == ntiles - 1) {
            const int q0 = qt * 64 + warp * 16 + g, q1 = q0 + 8;
            #pragma unroll
            for (int j = 0; j < 16; ++j) {
                int k0 = t * 128 + j * 8 + t2;
                if (!okqk(q0, k0))     s[j][0] = neg_inf();
                if (!okqk(q0, k0 + 1)) s[j][1] = neg_inf();
                if (!okqk(q1, k0))     s[j][2] = neg_inf();
                if (!okqk(q1, k0 + 1)) s[j][3] = neg_inf();
            }
        }

        float mx0 = neg_inf(), mx1 = neg_inf();
        #pragma unroll
        for (int j = 0; j < 16; ++j) {
            mx0 = fmaxf(mx0, fmaxf(s[j][0], s[j][1]));
            mx1 = fmaxf(mx1, fmaxf(s[j][2], s[j][3]));
        }
        mx0 = fmaxf(mx0, __shfl_xor_sync(0xffffffffu, mx0, 1));
        mx0 = fmaxf(mx0, __shfl_xor_sync(0xffffffffu, mx0, 2));
        mx1 = fmaxf(mx1, __shfl_xor_sync(0xffffffffu, mx1, 1));
        mx1 = fmaxf(mx1, __shfl_xor_sync(0xffffffffu, mx1, 2));

        const float mn0 = fmaxf(m0, mx0), mn1 = fmaxf(m1, mx1);
        const float sc0 = __expf(m0 - mn0), sc1 = __expf(m1 - mn1);
        m0 = mn0; m1 = mn1;

        float sum0 = 0.f, sum1 = 0.f;
        #pragma unroll
        for (int j = 0; j < 16; ++j) {
            s[j][0] = __expf(s[j][0] - mn0); sum0 += s[j][0];
            s[j][1] = __expf(s[j][1] - mn0); sum0 += s[j][1];
            s[j][2] = __expf(s[j][2] - mn1); sum1 += s[j][2];
            s[j][3] = __expf(s[j][3] - mn1); sum1 += s[j][3];
        }
        sum0 += __shfl_xor_sync(0xffffffffu, sum0, 1);
        sum0 += __shfl_xor_sync(0xffffffffu, sum0, 2);
        sum1 += __shfl_xor_sync(0xffffffffu, sum1, 1);
        sum1 += __shfl_xor_sync(0xffffffffu, sum1, 2);
        l0 = l0 * sc0 + sum0;
        l1 = l1 * sc1 + sum1;

        #pragma unroll
        for (int jn = 0; jn < 8; ++jn) {
            acc_o[jn][0] *= sc0; acc_o[jn][1] *= sc0;
            acc_o[jn][2] *= sc1; acc_o[jn][3] *= sc1;
        }

        #pragma unroll
        for (int ks = 0; ks < 8; ++ks) {
            uint32_t bv[8][2];
            #pragma unroll
            for (int jj = 0; jj < 4; ++jj) {
                uint32_t r[4];
                ldsm4(sV + (uint32_t)((jj*16 + b_row) * FA_PADV + ks*16 + b_k) * 2, r);
                bv[jj*2+0][0] = r[0]; bv[jj*2+0][1] = r[1];
                bv[jj*2+1][0] = r[2]; bv[jj*2+1][1] = r[3];
            }
            uint32_t pah[4];
            #pragma unroll
            for (int half = 0; half < 2; ++half) {
                const float* ps = s[2*ks + half];
                __half2 ah  = __halves2half2(__float2half(ps[0]), __float2half(ps[1]));
                __half2 bhv = __halves2half2(__float2half(ps[2]), __float2half(ps[3]));
                pah[half*2+0] = *reinterpret_cast<uint32_t*>(&ah);
                pah[half*2+1] = *reinterpret_cast<uint32_t*>(&bhv);
            }
            #pragma unroll
            for (int jn = 0; jn < 8; ++jn)
                mma16(acc_o[jn], pah, bv[jn]);
        }
        __syncthreads();
    }

    const float il0 = __frcp_rn(l0), il1 = __frcp_rn(l1);
    const int b = bh >> 4, h = bh & 15;
    const int q0 = qt * 64 + warp * 16 + g;
    #pragma unroll
    for (int jn = 0; jn < 8; ++jn)
        #pragma unroll
        for (int r = 0; r < 4; ++r) {
            int q = (r >= 2) ? q0 + 8 : q0;
            float v = acc_o[jn][r] * ((r >= 2) ? il1 : il0);
            int n = jn * 8 + t2 + (r & 1);
            size_t idx = ((size_t)(b * SEQ + q) * DIM) + h * HD + n;
            g_ch[idx] = __float2half(v);
        }
}

// ===========================================================================
extern "C" void kernel_launch(void* const* d_in, const int* in_sizes, int n_in,
                              void* d_out, int out_size)
{
    const float* x  = (const float*)d_in[0];
    const float* wq = (const float*)d_in[1];
    const float* wk = (const float*)d_in[2];
    const float* wv = (const float*)d_in[3];
    const float* wo = (const float*)d_in[4];
    const float* bo = (const float*)d_in[5];
    float* out = (float*)d_out;

    static bool attr_set = false;
    if (!attr_set) {
        cudaFuncSetAttribute(qkv_mma,    cudaFuncAttributeMaxDynamicSharedMemorySize, PRJ_SMEM);
        cudaFuncSetAttribute(out_mma,    cudaFuncAttributeMaxDynamicSharedMemorySize, PRJ_SMEM);
        cudaFuncSetAttribute(flash_attn, cudaFuncAttributeMaxDynamicSharedMemorySize, FA_SMEM);
        attr_set = true;
    }

    split_all<<<4096 + 4*1024, 256>>>(x, wq, wk, wv, wo);

    qkv_mma   <<<dim3(DIM/128, MROWS/128, 3), 256, PRJ_SMEM>>>();
    flash_attn<<<dim3(SEQ/64, BH), 128, FA_SMEM>>>();
    out_mma   <<<dim3(DIM/128, MROWS/128), 256, PRJ_SMEM>>>(bo, out);
}

// round 11
// speedup vs baseline: 1.4912x; 1.4912x over previous
#include <cuda_runtime.h>
#include <cuda_fp16.h>
#include <cstdint>

#define BATCH   8
#define SEQ     512
#define DIM     1024
#define HEADS   16
#define HD      64
#define NPATCH  196
#define MROWS   (BATCH*SEQ)     /* 4096 */
#define BH      (BATCH*HEADS)   /* 128  */

// ---------------- scratch (device globals: allocation-free) ----------------
__device__ __half g_xh [(size_t)MROWS*DIM];          // x hi
__device__ __half g_wh [(size_t)3*DIM*DIM];          // wq,wk,wv hi
__device__ __half g_woh[(size_t)DIM*DIM];            // wo hi
__device__ __half g_qh [(size_t)BH*SEQ*HD];          // Q hi (pre-scaled by 1/8)
__device__ __half g_kh [(size_t)BH*SEQ*HD];          // K hi
__device__ __half g_vh [(size_t)BH*HD*SEQ];          // V hi, [B,H,hd,S]
__device__ __half g_ch [(size_t)MROWS*DIM];          // ctx hi [B,S,D]

__device__ __forceinline__ float neg_inf() { return __int_as_float(0xff800000); }
__device__ __forceinline__ bool okqk(int q, int k)
{ return (q < NPATCH) ? (k < NPATCH) : (k <= q); }

// ===========================================================================
//  fused split kernel: x (4096 blocks) + 4 weights (1024 blocks each)
// ===========================================================================
__global__ __launch_bounds__(256) void split_all(const float* __restrict__ x,
                                                 const float* __restrict__ wq,
                                                 const float* __restrict__ wk,
                                                 const float* __restrict__ wv,
                                                 const float* __restrict__ wo)
{
    const float* src;
    __half* dst;
    size_t i;
    if (blockIdx.x < 4096) {
        src = x; dst = g_xh;
        i = (size_t)blockIdx.x * 256 + threadIdx.x;
    } else {
        int w = blockIdx.x - 4096;
        int seg = w >> 10;
        src = (seg == 0) ? wq : (seg == 1) ? wk : (seg == 2) ? wv : wo;
        dst = (seg < 3) ? g_wh + (size_t)seg * DIM * DIM : g_woh;
        i = (size_t)(w & 1023) * 256 + threadIdx.x;
    }
    float4 v = ((const float4*)src)[i];
    ((__half2*)dst)[i*2+0] = __halves2half2(__float2half(v.x), __float2half(v.y));
    ((__half2*)dst)[i*2+1] = __halves2half2(__float2half(v.z), __float2half(v.w));
}

// ===========================================================================
//  common utils
// ===========================================================================
__device__ __forceinline__ uint32_t smem_u32(const void* p)
{ return (uint32_t)__cvta_generic_to_shared(p); }

__device__ __forceinline__ void cp_async16(uint32_t s, const void* g)
{ asm volatile("cp.async.cg.shared.global [%0], [%1], 16;\n" :: "r"(s), "l"(g)); }

__device__ __forceinline__ void ldsm4(uint32_t addr, uint32_t* r)
{
    asm volatile("ldmatrix.sync.aligned.m8n8.x4.shared.b16 {%0,%1,%2,%3}, [%4];"
                 : "=r"(r[0]), "=r"(r[1]), "=r"(r[2]), "=r"(r[3]) : "r"(addr));
}

__device__ __forceinline__ void mma16(float* c, const uint32_t* a, const uint32_t* b)
{
    asm volatile(
        "mma.sync.aligned.m16n8k16.row.col.f32.f16.f16.f32 "
        "{%0,%1,%2,%3},{%4,%5,%6,%7},{%8,%9},{%0,%1,%2,%3};"
        : "+f"(c[0]), "+f"(c[1]), "+f"(c[2]), "+f"(c[3])
        : "r"(a[0]), "r"(a[1]), "r"(a[2]), "r"(a[3]), "r"(b[0]), "r"(b[1]));
}

// ===========================================================================
//  1-term fp16 128x128xK GEMM, 128-thread CTA, 4 warps (2M x 2N),
//  warp tile 64x64. 3-stage cp.async pipeline, 2 CTAs/SM.
// ===========================================================================
#define BK       32
#define PAD      40
#define A_TEH    (128*PAD)          /* halves per tile (A or B) */
#define STAGE_H  (2*A_TEH)          /* 10240 halves             */
#define PRJ_SMEM (3*STAGE_H*2)      /* 61440 bytes              */
#define PRJ_NKT  (DIM/BK)           /* 32                       */

__device__ __forceinline__ void gemm1(
    const __half* __restrict__ Ah, const __half* __restrict__ Bh,
    __half* sm, float (&acc)[4][8][4])
{
    const int tid  = threadIdx.x;
    const int warp = tid >> 5, lane = tid & 31;
    const int wm0  = (warp & 1) << 6;       // 0/64
    const int wn0  = (warp >> 1) << 6;      // 0/64
    const int a_row = (lane & 7) + ((lane >> 3) & 1) * 8;
    const int a_k   = ((lane >> 4) & 1) * 8;
    const int b_row = (lane & 7) + ((lane >> 4) & 1) * 8;
    const int b_k   = ((lane >> 3) & 1) * 8;
    const uint32_t sb = smem_u32(sm);

    auto load_stage = [&](int kt, int s) {
        uint32_t st = sb + (uint32_t)s * STAGE_H * 2;
        #pragma unroll
        for (int c = 0; c < 4; ++c) {
            int idx = tid + c * 128;            // 0..511
            int row = idx >> 2, ch = idx & 3;
            cp_async16(st + (uint32_t)(row * PAD + ch * 8) * 2,
                       Ah + (size_t)row * DIM + kt * BK + ch * 8);
            cp_async16(st + (uint32_t)(A_TEH + row * PAD + ch * 8) * 2,
                       Bh + (size_t)row * DIM + kt * BK + ch * 8);
        }
    };

    load_stage(0, 0);
    asm volatile("cp.async.commit_group;\n" ::: "memory");
    load_stage(1, 1);
    asm volatile("cp.async.commit_group;\n" ::: "memory");

    for (int kt = 0; kt < PRJ_NKT; ++kt) {
        const int cur = kt % 3;
        if (kt + 2 < PRJ_NKT) {
            load_stage(kt + 2, (kt + 2) % 3);
            asm volatile("cp.async.commit_group;\n" ::: "memory");
            asm volatile("cp.async.wait_group 2;\n" ::: "memory");
        } else if (kt + 1 < PRJ_NKT) {
            asm volatile("cp.async.wait_group 1;\n" ::: "memory");
        } else {
            asm volatile("cp.async.wait_group 0;\n" ::: "memory");
        }
        __syncthreads();

        const uint32_t st  = sb + (uint32_t)cur * STAGE_H * 2;
        const uint32_t sAh = st;
        const uint32_t sBh = st + A_TEH * 2;

        #pragma unroll
        for (int ks = 0; ks < BK; ks += 16) {
            uint32_t b[8][2];
            #pragma unroll
            for (int jj = 0; jj < 4; ++jj) {
                uint32_t r[4];
                ldsm4(sBh + (uint32_t)((wn0 + jj*16 + b_row) * PAD + ks + b_k) * 2, r);
                b[jj*2+0][0] = r[0]; b[jj*2+0][1] = r[1];
                b[jj*2+1][0] = r[2]; b[jj*2+1][1] = r[3];
            }
            uint32_t af[4][4];
            #pragma unroll
            for (int i = 0; i < 4; ++i)
                ldsm4(sAh + (uint32_t)((wm0 + i*16 + a_row) * PAD + ks + a_k) * 2, af[i]);
            #pragma unroll
            for (int i = 0; i < 4; ++i)
                #pragma unroll
                for (int j = 0; j < 8; ++j) mma16(acc[i][j], af[i], b[j]);
        }
        __syncthreads();
    }
}

// ---- 1) QKV projection: Q hi (scaled by 1/8), K hi, V hi transposed --------
__global__ __launch_bounds__(128, 2) void qkv_mma()
{
    extern __shared__ __half sm[];
    const int z = blockIdx.z;
    const __half* Ah = g_xh + (size_t)blockIdx.y * 128 * DIM;
    const __half* Bh = g_wh + (size_t)z * DIM * DIM + (size_t)blockIdx.x * 128 * DIM;

    float acc[4][8][4] = {};
    gemm1(Ah, Bh, sm, acc);

    const int warp = threadIdx.x >> 5, lane = threadIdx.x & 31;
    const int g = lane >> 2, t2 = (lane & 3) << 1;
    const int wm0 = (warp & 1) << 6, wn0 = (warp >> 1) << 6;
    #pragma unroll
    for (int i = 0; i < 4; ++i)
        #pragma unroll
        for (int j = 0; j < 8; ++j)
            #pragma unroll
            for (int r = 0; r < 4; ++r) {
                int m = blockIdx.y * 128 + wm0 + i * 16 + g + ((r >= 2) ? 8 : 0);
                int n = blockIdx.x * 128 + wn0 + j * 8 + t2 + (r & 1);
                int b = m >> 9, s = m & 511, h = n >> 6, d = n & 63;
                float v = acc[i][j][r];
                if (z == 0) {
                    size_t idx = ((size_t)(b * HEADS + h) * SEQ + s) * HD + d;
                    g_qh[idx] = __float2half(v * 0.125f);
                } else if (z == 1) {
                    size_t idx = ((size_t)(b * HEADS + h) * SEQ + s) * HD + d;
                    g_kh[idx] = __float2half(v);
                } else {
                    size_t idx = ((size_t)(b * HEADS + h) * HD + d) * SEQ + s;
                    g_vh[idx] = __float2half(v);
                }
            }
}

// ---- 5) out projection + bias ----------------------------------------------
__global__ __launch_bounds__(128, 2) void out_mma(const float* __restrict__ bo,
                                                  float* __restrict__ out)
{
    extern __shared__ __half sm[];
    const __half* Ah = g_ch + (size_t)blockIdx.y * 128 * DIM;
    const __half* Bh = g_woh + (size_t)blockIdx.x * 128 * DIM;

    float acc[4][8][4] = {};
    gemm1(Ah, Bh, sm, acc);

    const int warp = threadIdx.x >> 5, lane = threadIdx.x & 31;
    const int g = lane >> 2, t2 = (lane & 3) << 1;
    const int wm0 = (warp & 1) << 6, wn0 = (warp >> 1) << 6;
    #pragma unroll
    for (int i = 0; i < 4; ++i)
        #pragma unroll
        for (int j = 0; j < 8; ++j)
            #pragma unroll
            for (int r = 0; r < 4; ++r) {
                int m = blockIdx.y * 128 + wm0 + i * 16 + g + ((r >= 2) ? 8 : 0);
                int n = blockIdx.x * 128 + wn0 + j * 8 + t2 + (r & 1);
                out[(size_t)m * DIM + n] = acc[i][j][r] + bo[n];
            }
}

// ===========================================================================
//  fused flash attention: 128-thread CTA, 4 warps x 16 q rows (q-tile 64).
//  grid (8 qtiles, 128 bh) -> 1024 CTAs, 2 CTAs/SM.  (unchanged from R9)
// ===========================================================================
#define FA_PADK 72
#define FA_PADV 136
#define FA_KH   (128*FA_PADK)            /* halves */
#define FA_VT   (64*FA_PADV)
#define FA_STAGE_H (FA_KH + FA_VT)       /* 17920 halves */
#define FA_Q_H  (64*FA_PADK)             /* 4608 halves  */
#define FA_SMEM ((FA_Q_H + 2*FA_STAGE_H)*2)   /* 80896 B */

__global__ __launch_bounds__(128) void flash_attn()
{
    extern __shared__ __half fsm[];
    const int qt = blockIdx.x, bh = blockIdx.y;
    const int tid = threadIdx.x, warp = tid >> 5, lane = tid & 31;
    const int g = lane >> 2, t2 = (lane & 3) << 1;
    const int a_row = (lane & 7) + ((lane >> 3) & 1) * 8;
    const int a_k   = ((lane >> 4) & 1) * 8;
    const int b_row = (lane & 7) + ((lane >> 4) & 1) * 8;
    const int b_k   = ((lane >> 3) & 1) * 8;

    const int NT8[8] = {2, 2, 2, 2, 3, 3, 4, 4};
    const int ntiles = NT8[qt];

    const __half* Qh = g_qh + ((size_t)bh * SEQ + qt * 64) * HD;
    const __half* Kh = g_kh + (size_t)bh * SEQ * HD;
    const __half* Vt = g_vh + (size_t)bh * HD * SEQ;

    const uint32_t sb  = smem_u32(fsm);
    const uint32_t sQh = sb;
    const uint32_t sStg = sb + (uint32_t)FA_Q_H * 2;

    #pragma unroll
    for (int c = 0; c < 4; ++c) {
        int idx = tid + c * 128;
        int row = idx >> 3, ch = idx & 7;
        cp_async16(sQh + (uint32_t)(row * FA_PADK + ch * 8) * 2, Qh + (size_t)row * HD + ch * 8);
    }
    asm volatile("cp.async.commit_group;\n" ::: "memory");

    auto load_kv = [&](int t, int s) {
        uint32_t st = sStg + (uint32_t)s * FA_STAGE_H * 2;
        #pragma unroll
        for (int c = 0; c < 8; ++c) {
            int idx = tid + c * 128;
            int row = idx >> 3, ch = idx & 7;
            cp_async16(st + (uint32_t)(row * FA_PADK + ch * 8) * 2,
                       Kh + (size_t)(t * 128 + row) * HD + ch * 8);
        }
        uint32_t sv = st + (uint32_t)FA_KH * 2;
        #pragma unroll
        for (int c = 0; c < 8; ++c) {
            int idx = tid + c * 128;
            int row = idx >> 4, ch = idx & 15;
            cp_async16(sv + (uint32_t)(row * FA_PADV + ch * 8) * 2,
                       Vt + (size_t)row * SEQ + t * 128 + ch * 8);
        }
    };

    load_kv(0, 0);
    asm volatile("cp.async.commit_group;\n" ::: "memory");

    asm volatile("cp.async.wait_group 1;\n" ::: "memory");
    __syncthreads();
    uint32_t qfh[4][4];
    #pragma unroll
    for (int ks = 0; ks < 4; ++ks)
        ldsm4(sQh + (uint32_t)((warp * 16 + a_row) * FA_PADK + ks * 16 + a_k) * 2, qfh[ks]);

    float acc_o[8][4] = {};
    float m0 = neg_inf(), m1 = neg_inf(), l0 = 0.f, l1 = 0.f;

    for (int t = 0; t < ntiles; ++t) {
        if (t + 1 < ntiles) {
            load_kv(t + 1, (t + 1) & 1);
            asm volatile("cp.async.commit_group;\n" ::: "memory");
            asm volatile("cp.async.wait_group 1;\n" ::: "memory");
        } else {
            asm volatile("cp.async.wait_group 0;\n" ::: "memory");
        }
        __syncthreads();

        const uint32_t st = sStg + (uint32_t)(t & 1) * FA_STAGE_H * 2;
        const uint32_t sK = st;
        const uint32_t sV = st + (uint32_t)FA_KH * 2;

        float s[16][4];
        #pragma unroll
        for (int j = 0; j < 16; ++j)
            #pragma unroll
            for (int r = 0; r < 4; ++r) s[j][r] = 0.f;

        #pragma unroll
        for (int ks = 0; ks < 4; ++ks) {
            uint32_t bfr[16][2];
            #pragma unroll
            for (int jj = 0; jj < 8; ++jj) {
                uint32_t r[4];
                ldsm4(sK + (uint32_t)((jj*16 + b_row) * FA_PADK + ks*16 + b_k) * 2, r);
                bfr[jj*2+0][0] = r[0]; bfr[jj*2+0][1] = r[1];
                bfr[jj*2+1][0] = r[2]; bfr[jj*2+1][1] = r[3];
            }
            #pragma unroll
            for (int j = 0; j < 16; ++j)
                mma16(s[j], qfh[ks], bfr[j]);
        }

        if (t == ntiles - 1) {
            const int q0 = qt * 64 + warp * 16 + g, q1 = q0 + 8;
            #pragma unroll
            for (int j = 0; j < 16; ++j) {
                int k0 = t * 128 + j * 8 + t2;
                if (!okqk(q0, k0))     s[j][0] = neg_inf();
                if (!okqk(q0, k0 + 1)) s[j][1] = neg_inf();
                if (!okqk(q1, k0))     s[j][2] = neg_inf();
                if (!okqk(q1, k0 + 1)) s[j][3] = neg_inf();
            }
        }

        float mx0 = neg_inf(), mx1 = neg_inf();
        #pragma unroll
        for (int j = 0; j < 16; ++j) {
            mx0 = fmaxf(mx0, fmaxf(s[j][0], s[j][1]));
            mx1 = fmaxf(mx1, fmaxf(s[j][2], s[j][3]));
        }
        mx0 = fmaxf(mx0, __shfl_xor_sync(0xffffffffu, mx0, 1));
        mx0 = fmaxf(mx0, __shfl_xor_sync(0xffffffffu, mx0, 2));
        mx1 = fmaxf(mx1, __shfl_xor_sync(0xffffffffu, mx1, 1));
        mx1 = fmaxf(mx1, __shfl_xor_sync(0xffffffffu, mx1, 2));

        const float mn0 = fmaxf(m0, mx0), mn1 = fmaxf(m1, mx1);
        const float sc0 = __expf(m0 - mn0), sc1 = __expf(m1 - mn1);
        m0 = mn0; m1 = mn1;

        float sum0 = 0.f, sum1 = 0.f;
        #pragma unroll
        for (int j = 0; j < 16; ++j) {
            s[j][0] = __expf(s[j][0] - mn0); sum0 += s[j][0];
            s[j][1] = __expf(s[j][1] - mn0); sum0 += s[j][1];
            s[j][2] = __expf(s[j][2] - mn1); sum1 += s[j][2];
            s[j][3] = __expf(s[j][3] - mn1); sum1 += s[j][3];
        }
        sum0 += __shfl_xor_sync(0xffffffffu, sum0, 1);
        sum0 += __shfl_xor_sync(0xffffffffu, sum0, 2);
        sum1 += __shfl_xor_sync(0xffffffffu, sum1, 1);
        sum1 += __shfl_xor_sync(0xffffffffu, sum1, 2);
        l0 = l0 * sc0 + sum0;
        l1 = l1 * sc1 + sum1;

        #pragma unroll
        for (int jn = 0; jn < 8; ++jn) {
            acc_o[jn][0] *= sc0; acc_o[jn][1] *= sc0;
            acc_o[jn][2] *= sc1; acc_o[jn][3] *= sc1;
        }

        #pragma unroll
        for (int ks = 0; ks < 8; ++ks) {
            uint32_t bv[8][2];
            #pragma unroll
            for (int jj = 0; jj < 4; ++jj) {
                uint32_t r[4];
                ldsm4(sV + (uint32_t)((jj*16 + b_row) * FA_PADV + ks*16 + b_k) * 2, r);
                bv[jj*2+0][0] = r[0]; bv[jj*2+0][1] = r[1];
                bv[jj*2+1][0] = r[2]; bv[jj*2+1][1] = r[3];
            }
            uint32_t pah[4];
            #pragma unroll
            for (int half = 0; half < 2; ++half) {
                const float* ps = s[2*ks + half];
                __half2 ah  = __halves2half2(__float2half(ps[0]), __float2half(ps[1]));
                __half2 bhv = __halves2half2(__float2half(ps[2]), __float2half(ps[3]));
                pah[half*2+0] = *reinterpret_cast<uint32_t*>(&ah);
                pah[half*2+1] = *reinterpret_cast<uint32_t*>(&bhv);
            }
            #pragma unroll
            for (int jn = 0; jn < 8; ++jn)
                mma16(acc_o[jn], pah, bv[jn]);
        }
        __syncthreads();
    }

    const float il0 = __frcp_rn(l0), il1 = __frcp_rn(l1);
    const int b = bh >> 4, h = bh & 15;
    const int q0 = qt * 64 + warp * 16 + g;
    #pragma unroll
    for (int jn = 0; jn < 8; ++jn)
        #pragma unroll
        for (int r = 0; r < 4; ++r) {
            int q = (r >= 2) ? q0 + 8 : q0;
            float v = acc_o[jn][r] * ((r >= 2) ? il1 : il0);
            int n = jn * 8 + t2 + (r & 1);
            size_t idx = ((size_t)(b * SEQ + q) * DIM) + h * HD + n;
            g_ch[idx] = __float2half(v);
        }
}

// ===========================================================================
extern "C" void kernel_launch(void* const* d_in, const int* in_sizes, int n_in,
                              void* d_out, int out_size)
{
    const float* x  = (const float*)d_in[0];
    const float* wq = (const float*)d_in[1];
    const float* wk = (const float*)d_in[2];
    const float* wv = (const float*)d_in[3];
    const float* wo = (const float*)d_in[4];
    const float* bo = (const float*)d_in[5];
    float* out = (float*)d_out;

    static bool attr_set = false;
    if (!attr_set) {
        cudaFuncSetAttribute(qkv_mma,    cudaFuncAttributeMaxDynamicSharedMemorySize, PRJ_SMEM);
        cudaFuncSetAttribute(out_mma,    cudaFuncAttributeMaxDynamicSharedMemorySize, PRJ_SMEM);
        cudaFuncSetAttribute(flash_attn, cudaFuncAttributeMaxDynamicSharedMemorySize, FA_SMEM);
        attr_set = true;
    }

    split_all<<<4096 + 4*1024, 256>>>(x, wq, wk, wv, wo);

    qkv_mma   <<<dim3(DIM/128, MROWS/128, 3), 128, PRJ_SMEM>>>();
    flash_attn<<<dim3(SEQ/64, BH), 128, FA_SMEM>>>();
    out_mma   <<<dim3(DIM/128, MROWS/128), 128, PRJ_SMEM>>>(bo, out);
}

// round 12
// speedup vs baseline: 1.5515x; 1.0404x over previous
#include <cuda_runtime.h>
#include <cuda_fp16.h>
#include <cstdint>

#define BATCH   8
#define SEQ     512
#define DIM     1024
#define HEADS   16
#define HD      64
#define NPATCH  196
#define MROWS   (BATCH*SEQ)     /* 4096 */
#define BH      (BATCH*HEADS)   /* 128  */

// ---------------- scratch (device globals: allocation-free) ----------------
__device__ __half g_xh [(size_t)MROWS*DIM];          // x hi
__device__ __half g_wh [(size_t)3*DIM*DIM];          // wq,wk,wv hi
__device__ __half g_woh[(size_t)DIM*DIM];            // wo hi
__device__ __half g_qh [(size_t)BH*SEQ*HD];          // Q hi (pre-scaled by 1/8)
__device__ __half g_kh [(size_t)BH*SEQ*HD];          // K hi
__device__ __half g_vh [(size_t)BH*HD*SEQ];          // V hi, [B,H,hd,S]
__device__ __half g_ch [(size_t)MROWS*DIM];          // ctx hi [B,S,D]

__device__ __forceinline__ float neg_inf() { return __int_as_float(0xff800000); }
__device__ __forceinline__ bool okqk(int q, int k)
{ return (q < NPATCH) ? (k < NPATCH) : (k <= q); }

// ===========================================================================
//  fused split kernel: x (4096 blocks) + 4 weights (1024 blocks each)
// ===========================================================================
__global__ __launch_bounds__(256) void split_all(const float* __restrict__ x,
                                                 const float* __restrict__ wq,
                                                 const float* __restrict__ wk,
                                                 const float* __restrict__ wv,
                                                 const float* __restrict__ wo)
{
    const float* src;
    __half* dst;
    size_t i;
    if (blockIdx.x < 4096) {
        src = x; dst = g_xh;
        i = (size_t)blockIdx.x * 256 + threadIdx.x;
    } else {
        int w = blockIdx.x - 4096;
        int seg = w >> 10;
        src = (seg == 0) ? wq : (seg == 1) ? wk : (seg == 2) ? wv : wo;
        dst = (seg < 3) ? g_wh + (size_t)seg * DIM * DIM : g_woh;
        i = (size_t)(w & 1023) * 256 + threadIdx.x;
    }
    float4 v = ((const float4*)src)[i];
    ((__half2*)dst)[i*2+0] = __halves2half2(__float2half(v.x), __float2half(v.y));
    ((__half2*)dst)[i*2+1] = __halves2half2(__float2half(v.z), __float2half(v.w));
}

// ===========================================================================
//  common utils
// ===========================================================================
__device__ __forceinline__ uint32_t smem_u32(const void* p)
{ return (uint32_t)__cvta_generic_to_shared(p); }

__device__ __forceinline__ void cp_async16(uint32_t s, const void* g)
{ asm volatile("cp.async.cg.shared.global [%0], [%1], 16;\n" :: "r"(s), "l"(g)); }

__device__ __forceinline__ void ldsm4(uint32_t addr, uint32_t* r)
{
    asm volatile("ldmatrix.sync.aligned.m8n8.x4.shared.b16 {%0,%1,%2,%3}, [%4];"
                 : "=r"(r[0]), "=r"(r[1]), "=r"(r[2]), "=r"(r[3]) : "r"(addr));
}

__device__ __forceinline__ void mma16(float* c, const uint32_t* a, const uint32_t* b)
{
    asm volatile(
        "mma.sync.aligned.m16n8k16.row.col.f32.f16.f16.f32 "
        "{%0,%1,%2,%3},{%4,%5,%6,%7},{%8,%9},{%0,%1,%2,%3};"
        : "+f"(c[0]), "+f"(c[1]), "+f"(c[2]), "+f"(c[3])
        : "r"(a[0]), "r"(a[1]), "r"(a[2]), "r"(a[3]), "r"(b[0]), "r"(b[1]));
}

// ===========================================================================
//  1-term fp16 128x128xK GEMM, 128-thread CTA, 4 warps (2M x 2N),
//  warp tile 64x64. BK=64 (4 k16-steps/stage), 3-stage cp.async, 2 CTAs/SM.
// ===========================================================================
#define BK       64
#define PAD      72
#define A_TEH    (128*PAD)          /* 9216 halves per tile      */
#define STAGE_H  (2*A_TEH)          /* 18432 halves              */
#define PRJ_SMEM (3*STAGE_H*2)      /* 110592 bytes              */
#define PRJ_NKT  (DIM/BK)           /* 16                        */

__device__ __forceinline__ void gemm1(
    const __half* __restrict__ Ah, const __half* __restrict__ Bh,
    __half* sm, float (&acc)[4][8][4])
{
    const int tid  = threadIdx.x;
    const int warp = tid >> 5, lane = tid & 31;
    const int wm0  = (warp & 1) << 6;       // 0/64
    const int wn0  = (warp >> 1) << 6;      // 0/64
    const int a_row = (lane & 7) + ((lane >> 3) & 1) * 8;
    const int a_k   = ((lane >> 4) & 1) * 8;
    const int b_row = (lane & 7) + ((lane >> 4) & 1) * 8;
    const int b_k   = ((lane >> 3) & 1) * 8;
    const uint32_t sb = smem_u32(sm);

    auto load_stage = [&](int kt, int s) {
        uint32_t st = sb + (uint32_t)s * STAGE_H * 2;
        #pragma unroll
        for (int c = 0; c < 8; ++c) {
            int idx = tid + c * 128;            // 0..1023
            int row = idx >> 3, ch = idx & 7;
            cp_async16(st + (uint32_t)(row * PAD + ch * 8) * 2,
                       Ah + (size_t)row * DIM + kt * BK + ch * 8);
            cp_async16(st + (uint32_t)(A_TEH + row * PAD + ch * 8) * 2,
                       Bh + (size_t)row * DIM + kt * BK + ch * 8);
        }
    };

    load_stage(0, 0);
    asm volatile("cp.async.commit_group;\n" ::: "memory");
    load_stage(1, 1);
    asm volatile("cp.async.commit_group;\n" ::: "memory");

    for (int kt = 0; kt < PRJ_NKT; ++kt) {
        const int cur = kt % 3;
        if (kt + 2 < PRJ_NKT) {
            load_stage(kt + 2, (kt + 2) % 3);
            asm volatile("cp.async.commit_group;\n" ::: "memory");
            asm volatile("cp.async.wait_group 2;\n" ::: "memory");
        } else if (kt + 1 < PRJ_NKT) {
            asm volatile("cp.async.wait_group 1;\n" ::: "memory");
        } else {
            asm volatile("cp.async.wait_group 0;\n" ::: "memory");
        }
        __syncthreads();

        const uint32_t st  = sb + (uint32_t)cur * STAGE_H * 2;
        const uint32_t sAh = st;
        const uint32_t sBh = st + A_TEH * 2;

        #pragma unroll
        for (int ks = 0; ks < BK; ks += 16) {
            uint32_t b[8][2];
            #pragma unroll
            for (int jj = 0; jj < 4; ++jj) {
                uint32_t r[4];
                ldsm4(sBh + (uint32_t)((wn0 + jj*16 + b_row) * PAD + ks + b_k) * 2, r);
                b[jj*2+0][0] = r[0]; b[jj*2+0][1] = r[1];
                b[jj*2+1][0] = r[2]; b[jj*2+1][1] = r[3];
            }
            uint32_t af[4][4];
            #pragma unroll
            for (int i = 0; i < 4; ++i)
                ldsm4(sAh + (uint32_t)((wm0 + i*16 + a_row) * PAD + ks + a_k) * 2, af[i]);
            #pragma unroll
            for (int i = 0; i < 4; ++i)
                #pragma unroll
                for (int j = 0; j < 8; ++j) mma16(acc[i][j], af[i], b[j]);
        }
        __syncthreads();
    }
}

// ---- 1) QKV projection: Q hi (scaled by 1/8), K hi, V hi transposed --------
__global__ __launch_bounds__(128, 2) void qkv_mma()
{
    extern __shared__ __half sm[];
    const int z = blockIdx.z;
    const __half* Ah = g_xh + (size_t)blockIdx.y * 128 * DIM;
    const __half* Bh = g_wh + (size_t)z * DIM * DIM + (size_t)blockIdx.x * 128 * DIM;

    float acc[4][8][4] = {};
    gemm1(Ah, Bh, sm, acc);

    const int warp = threadIdx.x >> 5, lane = threadIdx.x & 31;
    const int g = lane >> 2, t2 = (lane & 3) << 1;
    const int wm0 = (warp & 1) << 6, wn0 = (warp >> 1) << 6;
    #pragma unroll
    for (int i = 0; i < 4; ++i)
        #pragma unroll
        for (int j = 0; j < 8; ++j)
            #pragma unroll
            for (int r = 0; r < 4; ++r) {
                int m = blockIdx.y * 128 + wm0 + i * 16 + g + ((r >= 2) ? 8 : 0);
                int n = blockIdx.x * 128 + wn0 + j * 8 + t2 + (r & 1);
                int b = m >> 9, s = m & 511, h = n >> 6, d = n & 63;
                float v = acc[i][j][r];
                if (z == 0) {
                    size_t idx = ((size_t)(b * HEADS + h) * SEQ + s) * HD + d;
                    g_qh[idx] = __float2half(v * 0.125f);
                } else if (z == 1) {
                    size_t idx = ((size_t)(b * HEADS + h) * SEQ + s) * HD + d;
                    g_kh[idx] = __float2half(v);
                } else {
                    size_t idx = ((size_t)(b * HEADS + h) * HD + d) * SEQ + s;
                    g_vh[idx] = __float2half(v);
                }
            }
}

// ---- 5) out projection + bias ----------------------------------------------
__global__ __launch_bounds__(128, 2) void out_mma(const float* __restrict__ bo,
                                                  float* __restrict__ out)
{
    extern __shared__ __half sm[];
    const __half* Ah = g_ch + (size_t)blockIdx.y * 128 * DIM;
    const __half* Bh = g_woh + (size_t)blockIdx.x * 128 * DIM;

    float acc[4][8][4] = {};
    gemm1(Ah, Bh, sm, acc);

    const int warp = threadIdx.x >> 5, lane = threadIdx.x & 31;
    const int g = lane >> 2, t2 = (lane & 3) << 1;
    const int wm0 = (warp & 1) << 6, wn0 = (warp >> 1) << 6;
    #pragma unroll
    for (int i = 0; i < 4; ++i)
        #pragma unroll
        for (int j = 0; j < 8; ++j)
            #pragma unroll
            for (int r = 0; r < 4; ++r) {
                int m = blockIdx.y * 128 + wm0 + i * 16 + g + ((r >= 2) ? 8 : 0);
                int n = blockIdx.x * 128 + wn0 + j * 8 + t2 + (r & 1);
                out[(size_t)m * DIM + n] = acc[i][j][r] + bo[n];
            }
}

// ===========================================================================
//  fused flash attention: 128-thread CTA, 4 warps x 16 q rows (q-tile 64).
//  grid (8 qtiles, 128 bh) -> 1024 CTAs, 2 CTAs/SM.  (unchanged from R11)
// ===========================================================================
#define FA_PADK 72
#define FA_PADV 136
#define FA_KH   (128*FA_PADK)            /* halves */
#define FA_VT   (64*FA_PADV)
#define FA_STAGE_H (FA_KH + FA_VT)       /* 17920 halves */
#define FA_Q_H  (64*FA_PADK)             /* 4608 halves  */
#define FA_SMEM ((FA_Q_H + 2*FA_STAGE_H)*2)   /* 80896 B */

__global__ __launch_bounds__(128) void flash_attn()
{
    extern __shared__ __half fsm[];
    const int qt = blockIdx.x, bh = blockIdx.y;
    const int tid = threadIdx.x, warp = tid >> 5, lane = tid & 31;
    const int g = lane >> 2, t2 = (lane & 3) << 1;
    const int a_row = (lane & 7) + ((lane >> 3) & 1) * 8;
    const int a_k   = ((lane >> 4) & 1) * 8;
    const int b_row = (lane & 7) + ((lane >> 4) & 1) * 8;
    const int b_k   = ((lane >> 3) & 1) * 8;

    const int NT8[8] = {2, 2, 2, 2, 3, 3, 4, 4};
    const int ntiles = NT8[qt];

    const __half* Qh = g_qh + ((size_t)bh * SEQ + qt * 64) * HD;
    const __half* Kh = g_kh + (size_t)bh * SEQ * HD;
    const __half* Vt = g_vh + (size_t)bh * HD * SEQ;

    const uint32_t sb  = smem_u32(fsm);
    const uint32_t sQh = sb;
    const uint32_t sStg = sb + (uint32_t)FA_Q_H * 2;

    #pragma unroll
    for (int c = 0; c < 4; ++c) {
        int idx = tid + c * 128;
        int row = idx >> 3, ch = idx & 7;
        cp_async16(sQh + (uint32_t)(row * FA_PADK + ch * 8) * 2, Qh + (size_t)row * HD + ch * 8);
    }
    asm volatile("cp.async.commit_group;\n" ::: "memory");

    auto load_kv = [&](int t, int s) {
        uint32_t st = sStg + (uint32_t)s * FA_STAGE_H * 2;
        #pragma unroll
        for (int c = 0; c < 8; ++c) {
            int idx = tid + c * 128;
            int row = idx >> 3, ch = idx & 7;
            cp_async16(st + (uint32_t)(row * FA_PADK + ch * 8) * 2,
                       Kh + (size_t)(t * 128 + row) * HD + ch * 8);
        }
        uint32_t sv = st + (uint32_t)FA_KH * 2;
        #pragma unroll
        for (int c = 0; c < 8; ++c) {
            int idx = tid + c * 128;
            int row = idx >> 4, ch = idx & 15;
            cp_async16(sv + (uint32_t)(row * FA_PADV + ch * 8) * 2,
                       Vt + (size_t)row * SEQ + t * 128 + ch * 8);
        }
    };

    load_kv(0, 0);
    asm volatile("cp.async.commit_group;\n" ::: "memory");

    asm volatile("cp.async.wait_group 1;\n" ::: "memory");
    __syncthreads();
    uint32_t qfh[4][4];
    #pragma unroll
    for (int ks = 0; ks < 4; ++ks)
        ldsm4(sQh + (uint32_t)((warp * 16 + a_row) * FA_PADK + ks * 16 + a_k) * 2, qfh[ks]);

    float acc_o[8][4] = {};
    float m0 = neg_inf(), m1 = neg_inf(), l0 = 0.f, l1 = 0.f;

    for (int t = 0; t < ntiles; ++t) {
        if (t + 1 < ntiles) {
            load_kv(t + 1, (t + 1) & 1);
            asm volatile("cp.async.commit_group;\n" ::: "memory");
            asm volatile("cp.async.wait_group 1;\n" ::: "memory");
        } else {
            asm volatile("cp.async.wait_group 0;\n" ::: "memory");
        }
        __syncthreads();

        const uint32_t st = sStg + (uint32_t)(t & 1) * FA_STAGE_H * 2;
        const uint32_t sK = st;
        const uint32_t sV = st + (uint32_t)FA_KH * 2;

        float s[16][4];
        #pragma unroll
        for (int j = 0; j < 16; ++j)
            #pragma unroll
            for (int r = 0; r < 4; ++r) s[j][r] = 0.f;

        #pragma unroll
        for (int ks = 0; ks < 4; ++ks) {
            uint32_t bfr[16][2];
            #pragma unroll
            for (int jj = 0; jj < 8; ++jj) {
                uint32_t r[4];
                ldsm4(sK + (uint32_t)((jj*16 + b_row) * FA_PADK + ks*16 + b_k) * 2, r);
                bfr[jj*2+0][0] = r[0]; bfr[jj*2+0][1] = r[1];
                bfr[jj*2+1][0] = r[2]; bfr[jj*2+1][1] = r[3];
            }
            #pragma unroll
            for (int j = 0; j < 16; ++j)
                mma16(s[j], qfh[ks], bfr[j]);
        }

        if (t == ntiles - 1) {
            const int q0 = qt * 64 + warp * 16 + g, q1 = q0 + 8;
            #pragma unroll
            for (int j = 0; j < 16; ++j) {
                int k0 = t * 128 + j * 8 + t2;
                if (!okqk(q0, k0))     s[j][0] = neg_inf();
                if (!okqk(q0, k0 + 1)) s[j][1] = neg_inf();
                if (!okqk(q1, k0))     s[j][2] = neg_inf();
                if (!okqk(q1, k0 + 1)) s[j][3] = neg_inf();
            }
        }

        float mx0 = neg_inf(), mx1 = neg_inf();
        #pragma unroll
        for (int j = 0; j < 16; ++j) {
            mx0 = fmaxf(mx0, fmaxf(s[j][0], s[j][1]));
            mx1 = fmaxf(mx1, fmaxf(s[j][2], s[j][3]));
        }
        mx0 = fmaxf(mx0, __shfl_xor_sync(0xffffffffu, mx0, 1));
        mx0 = fmaxf(mx0, __shfl_xor_sync(0xffffffffu, mx0, 2));
        mx1 = fmaxf(mx1, __shfl_xor_sync(0xffffffffu, mx1, 1));
        mx1 = fmaxf(mx1, __shfl_xor_sync(0xffffffffu, mx1, 2));

        const float mn0 = fmaxf(m0, mx0), mn1 = fmaxf(m1, mx1);
        const float sc0 = __expf(m0 - mn0), sc1 = __expf(m1 - mn1);
        m0 = mn0; m1 = mn1;

        float sum0 = 0.f, sum1 = 0.f;
        #pragma unroll
        for (int j = 0; j < 16; ++j) {
            s[j][0] = __expf(s[j][0] - mn0); sum0 += s[j][0];
            s[j][1] = __expf(s[j][1] - mn0); sum0 += s[j][1];
            s[j][2] = __expf(s[j][2] - mn1); sum1 += s[j][2];
            s[j][3] = __expf(s[j][3] - mn1); sum1 += s[j][3];
        }
        sum0 += __shfl_xor_sync(0xffffffffu, sum0, 1);
        sum0 += __shfl_xor_sync(0xffffffffu, sum0, 2);
        sum1 += __shfl_xor_sync(0xffffffffu, sum1, 1);
        sum1 += __shfl_xor_sync(0xffffffffu, sum1, 2);
        l0 = l0 * sc0 + sum0;
        l1 = l1 * sc1 + sum1;

        #pragma unroll
        for (int jn = 0; jn < 8; ++jn) {
            acc_o[jn][0] *= sc0; acc_o[jn][1] *= sc0;
            acc_o[jn][2] *= sc1; acc_o[jn][3] *= sc1;
        }

        #pragma unroll
        for (int ks = 0; ks < 8; ++ks) {
            uint32_t bv[8][2];
            #pragma unroll
            for (int jj = 0; jj < 4; ++jj) {
                uint32_t r[4];
                ldsm4(sV + (uint32_t)((jj*16 + b_row) * FA_PADV + ks*16 + b_k) * 2, r);
                bv[jj*2+0][0] = r[0]; bv[jj*2+0][1] = r[1];
                bv[jj*2+1][0] = r[2]; bv[jj*2+1][1] = r[3];
            }
            uint32_t pah[4];
            #pragma unroll
            for (int half = 0; half < 2; ++half) {
                const float* ps = s[2*ks + half];
                __half2 ah  = __halves2half2(__float2half(ps[0]), __float2half(ps[1]));
                __half2 bhv = __halves2half2(__float2half(ps[2]), __float2half(ps[3]));
                pah[half*2+0] = *reinterpret_cast<uint32_t*>(&ah);
                pah[half*2+1] = *reinterpret_cast<uint32_t*>(&bhv);
            }
            #pragma unroll
            for (int jn = 0; jn < 8; ++jn)
                mma16(acc_o[jn], pah, bv[jn]);
        }
        __syncthreads();
    }

    const float il0 = __frcp_rn(l0), il1 = __frcp_rn(l1);
    const int b = bh >> 4, h = bh & 15;
    const int q0 = qt * 64 + warp * 16 + g;
    #pragma unroll
    for (int jn = 0; jn < 8; ++jn)
        #pragma unroll
        for (int r = 0; r < 4; ++r) {
            int q = (r >= 2) ? q0 + 8 : q0;
            float v = acc_o[jn][r] * ((r >= 2) ? il1 : il0);
            int n = jn * 8 + t2 + (r & 1);
            size_t idx = ((size_t)(b * SEQ + q) * DIM) + h * HD + n;
            g_ch[idx] = __float2half(v);
        }
}

// ===========================================================================
extern "C" void kernel_launch(void* const* d_in, const int* in_sizes, int n_in,
                              void* d_out, int out_size)
{
    const float* x  = (const float*)d_in[0];
    const float* wq = (const float*)d_in[1];
    const float* wk = (const float*)d_in[2];
    const float* wv = (const float*)d_in[3];
    const float* wo = (const float*)d_in[4];
    const float* bo = (const float*)d_in[5];
    float* out = (float*)d_out;

    static bool attr_set = false;
    if (!attr_set) {
        cudaFuncSetAttribute(qkv_mma,    cudaFuncAttributeMaxDynamicSharedMemorySize, PRJ_SMEM);
        cudaFuncSetAttribute(out_mma,    cudaFuncAttributeMaxDynamicSharedMemorySize, PRJ_SMEM);
        cudaFuncSetAttribute(flash_attn, cudaFuncAttributeMaxDynamicSharedMemorySize, FA_SMEM);
        attr_set = true;
    }

    split_all<<<4096 + 4*1024, 256>>>(x, wq, wk, wv, wo);

    qkv_mma   <<<dim3(DIM/128, MROWS/128, 3), 128, PRJ_SMEM>>>();
    flash_attn<<<dim3(SEQ/64, BH), 128, FA_SMEM>>>();
    out_mma   <<<dim3(DIM/128, MROWS/128), 128, PRJ_SMEM>>>(bo, out);
}